// round 1
// baseline (speedup 1.0000x reference)
#include <cuda_runtime.h>
#include <math.h>

#define BB   64
#define INS  10000
#define EXPS 53
#define HID  1500
#define NC   2048
#define KX   (HID + EXPS)   // 1553
#define S1   12             // split-K for GEMM1
#define S2   5              // split-K for GEMM2

// Scratch (no cudaMalloc allowed) — fixed-order reductions, fully deterministic.
__device__ float g_part1[S1][BB][HID];   // GEMM1 split-K partials
__device__ float g_x[BB][KX];            // concat(gelu(h), exp_x)
__device__ float g_part2[S2][BB][NC];    // GEMM2 split-K partials
__device__ float g_flat[BB][NC];         // sigmoid output

// ---------------------------------------------------------------------------
// Tiled split-K GEMM: C_part[split] = A(64 x Kchunk) * B(Kchunk x 64-tile)
// Block = 256 threads, tile 64(M) x 64(N) x 16(K), 4x4 micro-tile per thread.
// ---------------------------------------------------------------------------
__global__ __launch_bounds__(256) void gemm64_splitk(
    const float* __restrict__ A, int lda,
    const float* __restrict__ Bm, int ldb,
    float* __restrict__ part, int N, int K, int kchunk)
{
    __shared__ float As[16][68];   // [kk][m], padded (+4) to soften store conflicts
    __shared__ float Bs[16][64];   // [kk][n]

    const int tid = threadIdx.x;
    const int tx  = tid & 15;      // N direction (4 cols each)
    const int ty  = tid >> 4;      // M direction (4 rows each)
    const int n0  = blockIdx.x * 64;
    const int k0  = blockIdx.y * kchunk;
    const int kend = min(k0 + kchunk, K);

    float acc[4][4];
    #pragma unroll
    for (int i = 0; i < 4; i++)
        #pragma unroll
        for (int j = 0; j < 4; j++) acc[i][j] = 0.f;

    for (int kt = k0; kt < kend; kt += 16) {
        __syncthreads();
        // A tile: 64 rows x 16 k  (coalesced 64B rows)
        #pragma unroll
        for (int i = tid; i < 64 * 16; i += 256) {
            int m = i >> 4, kk = i & 15;
            int k = kt + kk;
            As[kk][m] = (k < kend) ? A[m * lda + k] : 0.f;
        }
        // B tile: 16 k x 64 n  (fully coalesced)
        #pragma unroll
        for (int i = tid; i < 16 * 64; i += 256) {
            int kk = i >> 6, n = i & 63;
            int k = kt + kk;
            Bs[kk][n] = (k < kend && (n0 + n) < N)
                        ? Bm[(size_t)k * ldb + n0 + n] : 0.f;
        }
        __syncthreads();
        #pragma unroll
        for (int kk = 0; kk < 16; kk++) {
            float4 a4 = *(const float4*)&As[kk][ty * 4];
            float4 b4 = *(const float4*)&Bs[kk][tx * 4];
            float av[4] = {a4.x, a4.y, a4.z, a4.w};
            float bv[4] = {b4.x, b4.y, b4.z, b4.w};
            #pragma unroll
            for (int i = 0; i < 4; i++)
                #pragma unroll
                for (int j = 0; j < 4; j++)
                    acc[i][j] = fmaf(av[i], bv[j], acc[i][j]);
        }
    }

    float* pbase = part + (size_t)blockIdx.y * 64 * N;
    #pragma unroll
    for (int i = 0; i < 4; i++) {
        int m = ty * 4 + i;
        #pragma unroll
        for (int j = 0; j < 4; j++) {
            int n = n0 + tx * 4 + j;
            if (n < N) pbase[m * N + n] = acc[i][j];
        }
    }
}

// Reduce split-K partials + bias + exact GELU; also fuse the concat with exp_x.
__global__ void fuse1(const float* __restrict__ b1, const float* __restrict__ expx)
{
    int idx = blockIdx.x * 256 + threadIdx.x;
    if (idx >= BB * KX) return;
    int b = idx / KX, n = idx - b * KX;
    if (n < HID) {
        float s = b1[n];
        #pragma unroll
        for (int p = 0; p < S1; p++) s += g_part1[p][b][n];
        g_x[b][n] = 0.5f * s * (1.f + erff(s * 0.70710678118654752f));
    } else {
        g_x[b][n] = expx[b * EXPS + (n - HID)];
    }
}

// Reduce split-K partials + bias + sigmoid.
__global__ void fuse2(const float* __restrict__ b2)
{
    int idx = blockIdx.x * 256 + threadIdx.x;
    if (idx >= BB * NC) return;
    int b = idx >> 11, n = idx & (NC - 1);
    float s = b2[n];
    #pragma unroll
    for (int p = 0; p < S2; p++) s += g_part2[p][b][n];
    g_flat[b][n] = 1.f / (1.f + expf(-s));
}

// out[b,j] = flat[b,j] * max_i M[i,j]   (exact factorization: flat>0, M>=0)
__global__ void colmax_mul(const float* __restrict__ hpo, float* __restrict__ out)
{
    int j = blockIdx.x * 256 + threadIdx.x;   // j < NC
    float m0 = hpo[j];
    float m1 = hpo[NC + j];
    float m2 = hpo[2 * NC + j];
    float m3 = hpo[3 * NC + j];
    #pragma unroll 4
    for (int i = 4; i < NC; i += 4) {
        m0 = fmaxf(m0, hpo[(size_t)i       * NC + j]);
        m1 = fmaxf(m1, hpo[(size_t)(i + 1) * NC + j]);
        m2 = fmaxf(m2, hpo[(size_t)(i + 2) * NC + j]);
        m3 = fmaxf(m3, hpo[(size_t)(i + 3) * NC + j]);
    }
    float m = fmaxf(fmaxf(m0, m1), fmaxf(m2, m3));
    #pragma unroll 8
    for (int b = 0; b < BB; b++)
        out[b * NC + j] = g_flat[b][j] * m;
}

extern "C" void kernel_launch(void* const* d_in, const int* in_sizes, int n_in,
                              void* d_out, int out_size)
{
    const float* gos  = (const float*)d_in[0];
    const float* expx = (const float*)d_in[1];
    const float* W1   = (const float*)d_in[2];
    const float* b1   = (const float*)d_in[3];
    const float* W2   = (const float*)d_in[4];
    const float* b2   = (const float*)d_in[5];
    const float* hpo  = (const float*)d_in[6];
    float* out = (float*)d_out;

    float *p1, *px, *p2;
    cudaGetSymbolAddress((void**)&p1, g_part1);
    cudaGetSymbolAddress((void**)&px, g_x);
    cudaGetSymbolAddress((void**)&p2, g_part2);

    // GEMM1: (64 x 10000) @ (10000 x 1500)
    int kc1 = (INS + S1 - 1) / S1;
    dim3 g1((HID + 63) / 64, S1);
    gemm64_splitk<<<g1, 256>>>(gos, INS, W1, HID, p1, HID, INS, kc1);

    fuse1<<<(BB * KX + 255) / 256, 256>>>(b1, expx);

    // GEMM2: (64 x 1553) @ (1553 x 2048)
    int kc2 = (KX + S2 - 1) / S2;
    dim3 g2((NC + 63) / 64, S2);
    gemm64_splitk<<<g2, 256>>>(px, KX, W2, NC, p2, NC, KX, kc2);

    fuse2<<<(BB * NC + 255) / 256, 256>>>(b2);

    colmax_mul<<<NC / 256, 256>>>(hpo, out);
}